// round 8
// baseline (speedup 1.0000x reference)
#include <cuda_runtime.h>
#include <math.h>
#include <stdint.h>

#define TOKENS 4096
#define H 1024
#define IDIM 4096
#define NE 8
#define EROWS 4096                      // fixed rows per expert region (worst case)
#define EOSZ ((size_t)NE * EROWS * H)   // one split-K output buffer

// ---------------- scratch (static device globals; no runtime allocation) ----
__device__ float g_a[(size_t)NE * EROWS * H];       // 134 MB  A for GEMM1 (tf32, K-perm)
__device__ float g_h[(size_t)NE * EROWS * IDIM];    // 536 MB  gelu out (tf32, K-perm)
__device__ float g_eo[2 * EOSZ];                    // 268 MB  split-K partial outputs
__device__ float g_w1r[(size_t)NE * H * IDIM];      // 128 MB  w1 tf32, N-perm
__device__ float g_w2r[(size_t)NE * H * IDIM];      // 128 MB  w2 tf32, N-perm
__device__ int   g_cnt[NE];
__device__ int   g_te[TOKENS * 2];
__device__ int   g_ts[TOKENS * 2];
__device__ float g_tw[TOKENS * 2];

// ---------------- PTX helpers ----------------------------------------------
__device__ __forceinline__ float to_tf32(float x) {
    float r;
    asm("cvt.rna.tf32.f32 %0, %1;" : "=f"(r) : "f"(x));
    return r;
}
__device__ __forceinline__ void cpa16(uint32_t dst, const void* src) {
    asm volatile("cp.async.cg.shared.global [%0], [%1], 16;" :: "r"(dst), "l"(src));
}
__device__ __forceinline__ void cpa_commit() {
    asm volatile("cp.async.commit_group;" ::: "memory");
}
__device__ __forceinline__ void cpa_wait2() {
    asm volatile("cp.async.wait_group 2;" ::: "memory");
}
__device__ __forceinline__ void mma_tf32(float* d, uint32_t a0, uint32_t a1,
                                         uint32_t a2, uint32_t a3,
                                         float b0f, float b1f) {
    uint32_t b0 = __float_as_uint(b0f), b1 = __float_as_uint(b1f);
    asm volatile(
        "mma.sync.aligned.m16n8k8.row.col.f32.tf32.tf32.f32 "
        "{%0,%1,%2,%3},{%4,%5,%6,%7},{%8,%9},{%0,%1,%2,%3};"
        : "+f"(d[0]), "+f"(d[1]), "+f"(d[2]), "+f"(d[3])
        : "r"(a0), "r"(a1), "r"(a2), "r"(a3), "r"(b0), "r"(b1));
}

// A K-dim permutation within each 32-float block
__device__ __forceinline__ int perm_a(int k) {
    return (k & ~31) | ((k & 3) << 3) | ((k & 31) >> 2);
}
// B N-dim permutation within each 128-float block
__device__ __forceinline__ int perm_b(int n) {
    return (n & ~127) | (n & 64) | (((n >> 3) & 4) << 3) | ((n & 7) << 2)
         | ((n >> 3) & 3);
}

// ---------------- routing (+ direct A prep) ---------------------------------
__global__ void zero_counts_kernel() {
    if (threadIdx.x < NE) g_cnt[threadIdx.x] = 0;
}

__global__ void routing_kernel(const float* __restrict__ x,
                               const float* __restrict__ rlw,
                               const float* __restrict__ rlb,
                               const float* __restrict__ rw,
                               const float* __restrict__ rb,
                               const float* __restrict__ elw,
                               const float* __restrict__ elb) {
    int t = blockIdx.x;
    int tid = threadIdx.x;
    __shared__ float xs[H];
    __shared__ float red[8], red2[8];
    __shared__ float logits[NE];
    __shared__ float s_mu, s_rs;
    __shared__ int   se[2], ss[2];

    const float* xrow = x + (size_t)t * H;
    float s = 0.f, s2 = 0.f;
    for (int k = tid; k < H; k += 256) {
        float v = xrow[k];
        xs[k] = v;
        s += v; s2 += v * v;
    }
    for (int o = 16; o; o >>= 1) {
        s  += __shfl_down_sync(~0u, s, o);
        s2 += __shfl_down_sync(~0u, s2, o);
    }
    int w = tid >> 5, l = tid & 31;
    if (l == 0) { red[w] = s; red2[w] = s2; }
    __syncthreads();
    if (tid == 0) {
        float a = 0.f, b = 0.f;
        for (int i = 0; i < 8; i++) { a += red[i]; b += red2[i]; }
        float mu = a * (1.0f / H);
        float var = b * (1.0f / H) - mu * mu;
        s_mu = mu;
        s_rs = rsqrtf(var + 1e-5f);
    }
    __syncthreads();
    float mu = s_mu, rs = s_rs;
    for (int k = tid; k < H; k += 256)
        xs[k] = (xs[k] - mu) * rs;
    __syncthreads();
    if (w < NE) {
        float acc = 0.f;
        for (int k = l; k < H; k += 32) {
            float xln = xs[k] * rlw[k] + rlb[k];
            acc += xln * rw[k * NE + w];
        }
        for (int o = 16; o; o >>= 1) acc += __shfl_down_sync(~0u, acc, o);
        if (l == 0) logits[w] = acc + rb[w];
    }
    __syncthreads();
    if (tid == 0) {
        float v0 = -1e30f, v1 = -1e30f;
        int e0 = 0, e1 = 0;
        for (int e = 0; e < NE; e++) {
            float v = logits[e];
            if (v > v0)      { v1 = v0; e1 = e0; v0 = v; e0 = e; }
            else if (v > v1) { v1 = v;  e1 = e; }
        }
        float tt = expf(v1 - v0);
        float inv = 1.0f / (1.0f + tt);
        int s0 = atomicAdd(&g_cnt[e0], 1);
        int s1 = atomicAdd(&g_cnt[e1], 1);
        se[0] = e0; ss[0] = s0;
        se[1] = e1; ss[1] = s1;
        g_te[2 * t] = e0;     g_ts[2 * t] = s0;     g_tw[2 * t] = inv;
        g_te[2 * t + 1] = e1; g_ts[2 * t + 1] = s1; g_tw[2 * t + 1] = tt * inv;
    }
    __syncthreads();
#pragma unroll
    for (int j = 0; j < 2; j++) {
        int ee = se[j];
        float* dst = g_a + ((size_t)ee * EROWS + ss[j]) * H;
        const float* lw = elw + (size_t)ee * H;
        const float* lb = elb + (size_t)ee * H;
        for (int k = tid; k < H; k += 256)
            dst[perm_a(k)] = to_tf32(xs[k] * lw[k] + lb[k]);
    }
}

// Round weights to tf32 + permute N within 128-blocks
__global__ void prep_w_kernel(const float* __restrict__ src,
                              float* __restrict__ dst, int N) {
    size_t row = blockIdx.y;
    int n0 = blockIdx.x * 1024 + threadIdx.x * 4;
    float4 v = *(const float4*)(src + row * N + n0);
    float* d = dst + row * N;
    float vv[4] = {v.x, v.y, v.z, v.w};
#pragma unroll
    for (int j = 0; j < 4; j++)
        d[perm_b(n0 + j)] = to_tf32(vv[j]);
}

// ---------------- grouped GEMM via mma.sync tf32 ----------------------------
// Block tile 128x256, BK=32, 4-stage cp.async ring, one barrier per chunk,
// 8 warps = 2(M) x 4(N), warp tile 64x64.
#define ASS 36
#define BSS 264
#define ASTG (128 * ASS)
#define BSTG (32 * BSS)
#define STG  (ASTG + BSTG)
#define SMEM_DYN (4 * STG * 4)   // 208896 bytes

// MODE 0: GEMM1 A=g_a (K=1024), B=g_w1r, out=g_h (bias+gelu+tf32, K-perm)
// MODE 1: GEMM2 A=g_h (K=4096 split z*2048), B=g_w2r, out=g_eo[z] (no bias)
template <int MODE>
__global__ void __launch_bounds__(256, 1)
gemm_mma_kernel(const float* __restrict__ bias) {
    extern __shared__ float sm[];
    const int KTOT = (MODE == 0) ? H : IDIM;
    const int Kz   = (MODE == 0) ? H : (IDIM / 2);
    const int NO   = (MODE == 0) ? IDIM : H;

    int e = blockIdx.y >> 5;
    int mrow = (blockIdx.y & 31) << 7;
    int cnt = g_cnt[e];
    if (mrow >= cnt) return;
    int z = (MODE == 0) ? 0 : blockIdx.z;
    int k0 = z * Kz;
    int colBase = blockIdx.x * 256;

    const float* Asrc = ((MODE == 0) ? g_a : g_h)
                      + (size_t)(e * EROWS + mrow) * KTOT + k0;
    const float* Bsrc = ((MODE == 0) ? g_w1r : g_w2r)
                      + (size_t)e * ((size_t)H * IDIM) + (size_t)k0 * NO + colBase;

    int tid = threadIdx.x, lane = tid & 31, warp = tid >> 5;
    int wm = (warp & 1) << 6, wn = (warp >> 1) << 6;
    int g = lane >> 2, tg = lane & 3;

    uint32_t sU = (uint32_t)__cvta_generic_to_shared(sm);

    float acc[4][8][4];
#pragma unroll
    for (int mi = 0; mi < 4; mi++)
#pragma unroll
        for (int ni = 0; ni < 8; ni++)
#pragma unroll
            for (int q = 0; q < 4; q++) acc[mi][ni][q] = 0.f;

    const int NC = Kz / 32;

    auto issue = [&](int c) {
        uint32_t st = sU + (uint32_t)((c & 3) * (STG * 4));
        const float* ag = Asrc + c * 32;
#pragma unroll
        for (int j = 0; j < 4; j++) {
            int q = tid + 256 * j;
            int r = q >> 3, o = q & 7;
            cpa16(st + (uint32_t)(r * ASS + o * 4) * 4, ag + (size_t)r * KTOT + o * 4);
        }
        uint32_t bt = st + ASTG * 4;
        const float* bg = Bsrc + (size_t)(c * 32) * NO;
#pragma unroll
        for (int j = 0; j < 8; j++) {
            int q = tid + 256 * j;
            int r = q >> 6, o = q & 63;
            cpa16(bt + (uint32_t)(r * BSS + o * 4) * 4, bg + (size_t)r * NO + o * 4);
        }
    };

    issue(0); cpa_commit();
    issue(1); cpa_commit();
    issue(2); cpa_commit();

    for (int c = 0; c < NC; c++) {
        cpa_wait2();
        __syncthreads();
        const float* Ap = sm + (c & 3) * STG;
        const float* Bp = Ap + ASTG;
#pragma unroll
        for (int kp = 0; kp < 2; kp++) {
            float4 af[8];
#pragma unroll
            for (int j = 0; j < 8; j++)
                af[j] = *(const float4*)(Ap + (wm + 8 * j + g) * ASS + tg * 8 + kp * 4);
#pragma unroll
            for (int s = 0; s < 2; s++) {
                int kr = (kp * 2 + s) * 8 + tg;
                float4 q0 = *(const float4*)(Bp + kr * BSS + wn + 4 * g);
                float4 q1 = *(const float4*)(Bp + kr * BSS + wn + 4 * g + 32);
                float4 q2 = *(const float4*)(Bp + (kr + 4) * BSS + wn + 4 * g);
                float4 q3 = *(const float4*)(Bp + (kr + 4) * BSS + wn + 4 * g + 32);
                float b0a[8] = {q0.x, q0.y, q0.z, q0.w, q1.x, q1.y, q1.z, q1.w};
                float b1a[8] = {q2.x, q2.y, q2.z, q2.w, q3.x, q3.y, q3.z, q3.w};
#pragma unroll
                for (int ni = 0; ni < 8; ni++) {
#pragma unroll
                    for (int mi = 0; mi < 4; mi++) {
                        uint32_t a0, a1, a2, a3;
                        if (s == 0) {
                            a0 = __float_as_uint(af[2 * mi].x);
                            a1 = __float_as_uint(af[2 * mi + 1].x);
                            a2 = __float_as_uint(af[2 * mi].y);
                            a3 = __float_as_uint(af[2 * mi + 1].y);
                        } else {
                            a0 = __float_as_uint(af[2 * mi].z);
                            a1 = __float_as_uint(af[2 * mi + 1].z);
                            a2 = __float_as_uint(af[2 * mi].w);
                            a3 = __float_as_uint(af[2 * mi + 1].w);
                        }
                        mma_tf32(acc[mi][ni], a0, a1, a2, a3, b0a[ni], b1a[ni]);
                    }
                }
            }
        }
        if (c + 3 < NC) issue(c + 3);
        cpa_commit();
    }

    // ---------------- epilogue ----------------
#pragma unroll
    for (int mi = 0; mi < 4; mi++) {
        int lr0 = mrow + wm + 16 * mi + g;
        int lr1 = lr0 + 8;
        bool live0 = lr0 < cnt;
        bool live1 = lr1 < cnt;
        size_t grow0 = (size_t)(e * EROWS) + lr0;
        size_t grow1 = (size_t)(e * EROWS) + lr1;
#pragma unroll
        for (int ni = 0; ni < 8; ni++) {
            int gc = colBase + wn + 8 * ni + 2 * tg;
            float v0 = acc[mi][ni][0];
            float v1 = acc[mi][ni][1];
            float v2 = acc[mi][ni][2];
            float v3 = acc[mi][ni][3];
            if (MODE == 0) {
                float bv0 = bias[(size_t)e * NO + gc];
                float bv1 = bias[(size_t)e * NO + gc + 1];
                v0 += bv0; v1 += bv1; v2 += bv0; v3 += bv1;
                v0 = to_tf32(0.5f * v0 * (1.0f + erff(v0 * 0.70710678118654752f)));
                v1 = to_tf32(0.5f * v1 * (1.0f + erff(v1 * 0.70710678118654752f)));
                v2 = to_tf32(0.5f * v2 * (1.0f + erff(v2 * 0.70710678118654752f)));
                v3 = to_tf32(0.5f * v3 * (1.0f + erff(v3 * 0.70710678118654752f)));
                int i0 = perm_a(gc);
                int i1 = perm_a(gc + 1);
                if (live0) { g_h[grow0 * IDIM + i0] = v0; g_h[grow0 * IDIM + i1] = v1; }
                if (live1) { g_h[grow1 * IDIM + i0] = v2; g_h[grow1 * IDIM + i1] = v3; }
            } else {
                float* outp = g_eo + (size_t)z * EOSZ;
                if (live0) *(float2*)(outp + grow0 * H + gc) = make_float2(v0, v1);
                if (live1) *(float2*)(outp + grow1 * H + gc) = make_float2(v2, v3);
            }
        }
    }
}

// ---------------- finalize ---------------------------------------------------
__global__ void finalize_kernel(const float* __restrict__ olw,
                                const float* __restrict__ olb,
                                const float* __restrict__ b2,
                                float* __restrict__ out) {
    int t = blockIdx.x;
    int tid = threadIdx.x;
    __shared__ float cs[H];
    __shared__ float red[8], red2[8];
    __shared__ float s_mu, s_rs;

    int e0 = g_te[2 * t], e1 = g_te[2 * t + 1];
    size_t row0 = (size_t)e0 * EROWS + g_ts[2 * t];
    size_t row1 = (size_t)e1 * EROWS + g_ts[2 * t + 1];
    float w0 = g_tw[2 * t], w1v = g_tw[2 * t + 1];
    const float* rA0 = g_eo + row0 * H;
    const float* rB0 = g_eo + EOSZ + row0 * H;
    const float* rA1 = g_eo + row1 * H;
    const float* rB1 = g_eo + EOSZ + row1 * H;
    const float* bb0 = b2 + (size_t)e0 * H;
    const float* bb1 = b2 + (size_t)e1 * H;

    float s = 0.f, s2 = 0.f;
    for (int k = tid; k < H; k += 256) {
        float u0 = rA0[k] + rB0[k] + bb0[k];
        float u1 = rA1[k] + rB1[k] + bb1[k];
        float v = w0 * u0 + w1v * u1;
        cs[k] = v;
        s += v; s2 += v * v;
    }
    for (int o = 16; o; o >>= 1) {
        s  += __shfl_down_sync(~0u, s, o);
        s2 += __shfl_down_sync(~0u, s2, o);
    }
    int w = tid >> 5, l = tid & 31;
    if (l == 0) { red[w] = s; red2[w] = s2; }
    __syncthreads();
    if (tid == 0) {
        float a = 0.f, b = 0.f;
        for (int i = 0; i < 8; i++) { a += red[i]; b += red2[i]; }
        float mu = a * (1.0f / H);
        float var = b * (1.0f / H) - mu * mu;
        s_mu = mu;
        s_rs = rsqrtf(var + 1e-5f);
    }
    __syncthreads();
    float mu = s_mu, rs = s_rs;
    for (int k = tid; k < H; k += 256) {
        out[(size_t)t * H + k] = (cs[k] - mu) * rs * olw[k] + olb[k];
    }
}

// ---------------- launch -----------------------------------------------------
extern "C" void kernel_launch(void* const* d_in, const int* in_sizes, int n_in,
                              void* d_out, int out_size) {
    const float* x   = (const float*)d_in[0];
    const float* rlw = (const float*)d_in[1];
    const float* rlb = (const float*)d_in[2];
    const float* rw  = (const float*)d_in[3];
    const float* rb  = (const float*)d_in[4];
    const float* elw = (const float*)d_in[5];
    const float* elb = (const float*)d_in[6];
    const float* w1  = (const float*)d_in[7];
    const float* b1  = (const float*)d_in[8];
    const float* w2  = (const float*)d_in[9];
    const float* b2  = (const float*)d_in[10];
    const float* olw = (const float*)d_in[11];
    const float* olb = (const float*)d_in[12];
    float* out = (float*)d_out;

    static int attr_set = 0;
    if (!attr_set) {
        cudaFuncSetAttribute(gemm_mma_kernel<0>,
                             cudaFuncAttributeMaxDynamicSharedMemorySize, SMEM_DYN);
        cudaFuncSetAttribute(gemm_mma_kernel<1>,
                             cudaFuncAttributeMaxDynamicSharedMemorySize, SMEM_DYN);
        attr_set = 1;
    }

    float* w1r; cudaGetSymbolAddress((void**)&w1r, g_w1r);
    float* w2r; cudaGetSymbolAddress((void**)&w2r, g_w2r);

    zero_counts_kernel<<<1, 32>>>();
    routing_kernel<<<TOKENS, 256>>>(x, rlw, rlb, rw, rb, elw, elb);
    prep_w_kernel<<<dim3(IDIM / 1024, NE * H), 256>>>(w1, w1r, IDIM);
    prep_w_kernel<<<dim3(H / 1024, NE * IDIM), 256>>>(w2, w2r, H);
    gemm_mma_kernel<0><<<dim3(IDIM / 256, NE * 32), 256, SMEM_DYN>>>(b1);
    gemm_mma_kernel<1><<<dim3(H / 256, NE * 32, 2), 256, SMEM_DYN>>>(b2);
    finalize_kernel<<<TOKENS, 256>>>(olw, olb, b2, out);
}

// round 9
// speedup vs baseline: 1.6904x; 1.6904x over previous
#include <cuda_runtime.h>
#include <cuda_fp16.h>
#include <math.h>
#include <stdint.h>

#define TOKENS 4096
#define H 1024
#define IDIM 4096
#define NE 8
#define EROWS 4096                      // fixed rows per expert region (worst case)
#define EOSZ ((size_t)NE * EROWS * H)   // one split-K output buffer

// ---------------- scratch (static device globals; no runtime allocation) ----
__device__ __half g_a[(size_t)NE * EROWS * H];       // 67 MB   A for GEMM1 (fp16, K-perm)
__device__ __half g_h[(size_t)NE * EROWS * IDIM];    // 268 MB  gelu out (fp16, K-perm)
__device__ float  g_eo[2 * EOSZ];                    // 268 MB  split-K partial outputs
__device__ __half g_w1r[(size_t)NE * H * IDIM];      // 64 MB   w1 fp16, [e][n][K] K-perm
__device__ __half g_w2r[(size_t)NE * H * IDIM];      // 64 MB   w2 fp16, [e][n][K] K-perm
__device__ int    g_cnt[NE];
__device__ int    g_te[TOKENS * 2];
__device__ int    g_ts[TOKENS * 2];
__device__ float  g_tw[TOKENS * 2];

// ---------------- PTX helpers ----------------------------------------------
__device__ __forceinline__ void cpa16(uint32_t dst, const void* src) {
    asm volatile("cp.async.cg.shared.global [%0], [%1], 16;" :: "r"(dst), "l"(src));
}
__device__ __forceinline__ void cpa_commit() {
    asm volatile("cp.async.commit_group;" ::: "memory");
}
__device__ __forceinline__ void cpa_wait2() {
    asm volatile("cp.async.wait_group 2;" ::: "memory");
}
__device__ __forceinline__ void mma_fp16(float* d, uint32_t a0, uint32_t a1,
                                         uint32_t a2, uint32_t a3,
                                         uint32_t b0, uint32_t b1) {
    asm volatile(
        "mma.sync.aligned.m16n8k16.row.col.f32.f16.f16.f32 "
        "{%0,%1,%2,%3},{%4,%5,%6,%7},{%8,%9},{%0,%1,%2,%3};"
        : "+f"(d[0]), "+f"(d[1]), "+f"(d[2]), "+f"(d[3])
        : "r"(a0), "r"(a1), "r"(a2), "r"(a3), "r"(b0), "r"(b1));
}

// K interleave within each 32-element chunk so per-thread fragments are 16B:
// thread tg owns halfs [tg*8 .. tg*8+7] = {ks0: k=2tg,2tg+1,2tg+8,2tg+9 | ks1: +16}
__device__ __forceinline__ int perm_k(int k) {
    int k16 = k & 15, ks = (k >> 4) & 1;
    int p = (((k16 & 7) >> 1) << 2) | (((k16 >> 3) & 1) << 1) | (k16 & 1);
    int posc = ((p >> 2) << 3) | (ks << 2) | (p & 3);
    return (k & ~31) | posc;
}

// ---------------- routing (+ direct A prep) ---------------------------------
__global__ void zero_counts_kernel() {
    if (threadIdx.x < NE) g_cnt[threadIdx.x] = 0;
}

__global__ void routing_kernel(const float* __restrict__ x,
                               const float* __restrict__ rlw,
                               const float* __restrict__ rlb,
                               const float* __restrict__ rw,
                               const float* __restrict__ rb,
                               const float* __restrict__ elw,
                               const float* __restrict__ elb) {
    int t = blockIdx.x;
    int tid = threadIdx.x;
    __shared__ float xs[H];
    __shared__ float red[8], red2[8];
    __shared__ float logits[NE];
    __shared__ float s_mu, s_rs;
    __shared__ int   se[2], ss[2];

    const float* xrow = x + (size_t)t * H;
    float s = 0.f, s2 = 0.f;
    for (int k = tid; k < H; k += 256) {
        float v = xrow[k];
        xs[k] = v;
        s += v; s2 += v * v;
    }
    for (int o = 16; o; o >>= 1) {
        s  += __shfl_down_sync(~0u, s, o);
        s2 += __shfl_down_sync(~0u, s2, o);
    }
    int w = tid >> 5, l = tid & 31;
    if (l == 0) { red[w] = s; red2[w] = s2; }
    __syncthreads();
    if (tid == 0) {
        float a = 0.f, b = 0.f;
        for (int i = 0; i < 8; i++) { a += red[i]; b += red2[i]; }
        float mu = a * (1.0f / H);
        float var = b * (1.0f / H) - mu * mu;
        s_mu = mu;
        s_rs = rsqrtf(var + 1e-5f);
    }
    __syncthreads();
    float mu = s_mu, rs = s_rs;
    for (int k = tid; k < H; k += 256)
        xs[k] = (xs[k] - mu) * rs;
    __syncthreads();
    if (w < NE) {
        float acc = 0.f;
        for (int k = l; k < H; k += 32) {
            float xln = xs[k] * rlw[k] + rlb[k];
            acc += xln * rw[k * NE + w];
        }
        for (int o = 16; o; o >>= 1) acc += __shfl_down_sync(~0u, acc, o);
        if (l == 0) logits[w] = acc + rb[w];
    }
    __syncthreads();
    if (tid == 0) {
        float v0 = -1e30f, v1 = -1e30f;
        int e0 = 0, e1 = 0;
        for (int e = 0; e < NE; e++) {
            float v = logits[e];
            if (v > v0)      { v1 = v0; e1 = e0; v0 = v; e0 = e; }
            else if (v > v1) { v1 = v;  e1 = e; }
        }
        float tt = expf(v1 - v0);
        float inv = 1.0f / (1.0f + tt);
        int s0 = atomicAdd(&g_cnt[e0], 1);
        int s1 = atomicAdd(&g_cnt[e1], 1);
        se[0] = e0; ss[0] = s0;
        se[1] = e1; ss[1] = s1;
        g_te[2 * t] = e0;     g_ts[2 * t] = s0;     g_tw[2 * t] = inv;
        g_te[2 * t + 1] = e1; g_ts[2 * t + 1] = s1; g_tw[2 * t + 1] = tt * inv;
    }
    __syncthreads();
#pragma unroll
    for (int j = 0; j < 2; j++) {
        int ee = se[j];
        __half* dst = g_a + ((size_t)ee * EROWS + ss[j]) * H;
        const float* lw = elw + (size_t)ee * H;
        const float* lb = elb + (size_t)ee * H;
        for (int k = tid * 2; k < H; k += 512) {
            float f0 = xs[k] * lw[k] + lb[k];
            float f1 = xs[k + 1] * lw[k + 1] + lb[k + 1];
            *(__half2*)(dst + perm_k(k)) = __floats2half2_rn(f0, f1);
        }
    }
}

// Transpose weights [K][N] fp32 -> [N][K] fp16 with K-chunk interleave
__global__ void prep_w_kernel(const float* __restrict__ src,
                              __half* __restrict__ dst, int K, int N) {
    __shared__ float t[32][33];
    int e = blockIdx.z;
    src += (size_t)e * K * N;
    dst += (size_t)e * K * N;
    int k0 = blockIdx.x * 32, n0 = blockIdx.y * 32;
    int idx = threadIdx.x;
    int kr = idx >> 3, nc4 = (idx & 7) * 4;
    float4 v = *(const float4*)(src + (size_t)(k0 + kr) * N + n0 + nc4);
    t[kr][nc4 + 0] = v.x; t[kr][nc4 + 1] = v.y;
    t[kr][nc4 + 2] = v.z; t[kr][nc4 + 3] = v.w;
    __syncthreads();
    int n = idx >> 3;
    int p0 = (idx & 7) * 2;
#pragma unroll
    for (int j = 0; j < 2; j++) {
        int kp = (p0 + j) * 2;
        __half2 h = __floats2half2_rn(t[kp][n], t[kp + 1][n]);
        *(__half2*)(dst + (size_t)(n0 + n) * K + perm_k(k0 + kp)) = h;
    }
}

// ---------------- grouped GEMM via mma.sync fp16 ----------------------------
// Block tile 128x256, BK=32, 4-stage cp.async ring, 8 warps = 2(M) x 4(N),
// warp tile 64x64. A smem [128][32]h, B smem [256][32]h (n-major).
#define ATILE_B 8192
#define BTILE_B 16384
#define STGB (ATILE_B + BTILE_B)
#define SMEM_DYN (4 * STGB)   // 98304 bytes

// MODE 0: GEMM1 A=g_a (K=1024), B=g_w1r, out=g_h (bias+gelu, fp16 K-perm)
// MODE 1: GEMM2 A=g_h (K=4096 split z*2048), B=g_w2r, out=g_eo[z] fp32
template <int MODE>
__global__ void __launch_bounds__(256, 1)
gemm_mma_kernel(const float* __restrict__ bias) {
    extern __shared__ char smc[];
    const int KTOT = (MODE == 0) ? H : IDIM;
    const int Kz   = (MODE == 0) ? H : (IDIM / 2);
    const int NO   = (MODE == 0) ? IDIM : H;

    int e = blockIdx.y >> 5;
    int mrow = (blockIdx.y & 31) << 7;
    int cnt = g_cnt[e];
    if (mrow >= cnt) return;
    int z = (MODE == 0) ? 0 : blockIdx.z;
    int k0 = z * Kz;
    int colBase = blockIdx.x * 256;

    const __half* Asrc = ((MODE == 0) ? g_a : g_h)
                       + (size_t)(e * EROWS + mrow) * KTOT + k0;
    const __half* Bsrc = ((MODE == 0) ? g_w1r : g_w2r)
                       + (size_t)e * ((size_t)H * IDIM)
                       + (size_t)colBase * KTOT + k0;

    int tid = threadIdx.x, lane = tid & 31, warp = tid >> 5;
    int wm = (warp & 1) << 6, wn = (warp >> 1) << 6;
    int g = lane >> 2, tg = lane & 3;

    uint32_t sU = (uint32_t)__cvta_generic_to_shared(smc);

    float acc[4][8][4];
#pragma unroll
    for (int mi = 0; mi < 4; mi++)
#pragma unroll
        for (int ni = 0; ni < 8; ni++)
#pragma unroll
            for (int q = 0; q < 4; q++) acc[mi][ni][q] = 0.f;

    const int NC = Kz / 32;

    auto issue = [&](int c) {
        uint32_t st = sU + (uint32_t)((c & 3) * STGB);
        const __half* ag = Asrc + c * 32;
#pragma unroll
        for (int j = 0; j < 2; j++) {
            int q = tid + 256 * j;
            int r = q >> 2, o = q & 3;
            cpa16(st + (uint32_t)(r * 64 + o * 16), ag + (size_t)r * KTOT + o * 8);
        }
        uint32_t bt = st + ATILE_B;
        const __half* bg = Bsrc + c * 32;
#pragma unroll
        for (int j = 0; j < 4; j++) {
            int q = tid + 256 * j;
            int r = q >> 2, o = q & 3;
            cpa16(bt + (uint32_t)(r * 64 + o * 16), bg + (size_t)r * KTOT + o * 8);
        }
    };

    issue(0); cpa_commit();
    issue(1); cpa_commit();
    issue(2); cpa_commit();

    for (int c = 0; c < NC; c++) {
        cpa_wait2();
        __syncthreads();
        const __half* Ap = (const __half*)(smc + (c & 3) * STGB);
        const __half* Bp = (const __half*)(smc + (c & 3) * STGB + ATILE_B);

        uint4 Au[4][2];
#pragma unroll
        for (int mi = 0; mi < 4; mi++) {
            Au[mi][0] = *(const uint4*)(Ap + (wm + 16 * mi + g) * 32 + tg * 8);
            Au[mi][1] = *(const uint4*)(Ap + (wm + 16 * mi + 8 + g) * 32 + tg * 8);
        }
#pragma unroll
        for (int ni = 0; ni < 8; ni++) {
            uint4 Bv = *(const uint4*)(Bp + (wn + 8 * ni + g) * 32 + tg * 8);
#pragma unroll
            for (int mi = 0; mi < 4; mi++) {
                mma_fp16(acc[mi][ni], Au[mi][0].x, Au[mi][1].x,
                         Au[mi][0].y, Au[mi][1].y, Bv.x, Bv.y);
                mma_fp16(acc[mi][ni], Au[mi][0].z, Au[mi][1].z,
                         Au[mi][0].w, Au[mi][1].w, Bv.z, Bv.w);
            }
        }
        if (c + 3 < NC) issue(c + 3);
        cpa_commit();
    }

    // ---------------- epilogue ----------------
#pragma unroll
    for (int mi = 0; mi < 4; mi++) {
        int lr0 = mrow + wm + 16 * mi + g;
        int lr1 = lr0 + 8;
        bool live0 = lr0 < cnt;
        bool live1 = lr1 < cnt;
        size_t grow0 = (size_t)(e * EROWS) + lr0;
        size_t grow1 = (size_t)(e * EROWS) + lr1;
#pragma unroll
        for (int ni = 0; ni < 8; ni++) {
            int gc = colBase + wn + 8 * ni + 2 * tg;
            float v0 = acc[mi][ni][0];
            float v1 = acc[mi][ni][1];
            float v2 = acc[mi][ni][2];
            float v3 = acc[mi][ni][3];
            if (MODE == 0) {
                float bv0 = bias[(size_t)e * NO + gc];
                float bv1 = bias[(size_t)e * NO + gc + 1];
                v0 += bv0; v1 += bv1; v2 += bv0; v3 += bv1;
                v0 = 0.5f * v0 * (1.0f + erff(v0 * 0.70710678118654752f));
                v1 = 0.5f * v1 * (1.0f + erff(v1 * 0.70710678118654752f));
                v2 = 0.5f * v2 * (1.0f + erff(v2 * 0.70710678118654752f));
                v3 = 0.5f * v3 * (1.0f + erff(v3 * 0.70710678118654752f));
                int i0 = perm_k(gc);
                if (live0)
                    *(__half2*)(g_h + grow0 * IDIM + i0) = __floats2half2_rn(v0, v1);
                if (live1)
                    *(__half2*)(g_h + grow1 * IDIM + i0) = __floats2half2_rn(v2, v3);
            } else {
                float* outp = g_eo + (size_t)z * EOSZ;
                if (live0) *(float2*)(outp + grow0 * H + gc) = make_float2(v0, v1);
                if (live1) *(float2*)(outp + grow1 * H + gc) = make_float2(v2, v3);
            }
        }
    }
}

// ---------------- finalize ---------------------------------------------------
__global__ void finalize_kernel(const float* __restrict__ olw,
                                const float* __restrict__ olb,
                                const float* __restrict__ b2,
                                float* __restrict__ out) {
    int t = blockIdx.x;
    int tid = threadIdx.x;
    __shared__ float cs[H];
    __shared__ float red[8], red2[8];
    __shared__ float s_mu, s_rs;

    int e0 = g_te[2 * t], e1 = g_te[2 * t + 1];
    size_t row0 = (size_t)e0 * EROWS + g_ts[2 * t];
    size_t row1 = (size_t)e1 * EROWS + g_ts[2 * t + 1];
    float w0 = g_tw[2 * t], w1v = g_tw[2 * t + 1];
    const float* rA0 = g_eo + row0 * H;
    const float* rB0 = g_eo + EOSZ + row0 * H;
    const float* rA1 = g_eo + row1 * H;
    const float* rB1 = g_eo + EOSZ + row1 * H;
    const float* bb0 = b2 + (size_t)e0 * H;
    const float* bb1 = b2 + (size_t)e1 * H;

    float s = 0.f, s2 = 0.f;
    for (int k = tid; k < H; k += 256) {
        float u0 = rA0[k] + rB0[k] + bb0[k];
        float u1 = rA1[k] + rB1[k] + bb1[k];
        float v = w0 * u0 + w1v * u1;
        cs[k] = v;
        s += v; s2 += v * v;
    }
    for (int o = 16; o; o >>= 1) {
        s  += __shfl_down_sync(~0u, s, o);
        s2 += __shfl_down_sync(~0u, s2, o);
    }
    int w = tid >> 5, l = tid & 31;
    if (l == 0) { red[w] = s; red2[w] = s2; }
    __syncthreads();
    if (tid == 0) {
        float a = 0.f, b = 0.f;
        for (int i = 0; i < 8; i++) { a += red[i]; b += red2[i]; }
        float mu = a * (1.0f / H);
        float var = b * (1.0f / H) - mu * mu;
        s_mu = mu;
        s_rs = rsqrtf(var + 1e-5f);
    }
    __syncthreads();
    float mu = s_mu, rs = s_rs;
    for (int k = tid; k < H; k += 256) {
        out[(size_t)t * H + k] = (cs[k] - mu) * rs * olw[k] + olb[k];
    }
}

// ---------------- launch -----------------------------------------------------
extern "C" void kernel_launch(void* const* d_in, const int* in_sizes, int n_in,
                              void* d_out, int out_size) {
    const float* x   = (const float*)d_in[0];
    const float* rlw = (const float*)d_in[1];
    const float* rlb = (const float*)d_in[2];
    const float* rw  = (const float*)d_in[3];
    const float* rb  = (const float*)d_in[4];
    const float* elw = (const float*)d_in[5];
    const float* elb = (const float*)d_in[6];
    const float* w1  = (const float*)d_in[7];
    const float* b1  = (const float*)d_in[8];
    const float* w2  = (const float*)d_in[9];
    const float* b2  = (const float*)d_in[10];
    const float* olw = (const float*)d_in[11];
    const float* olb = (const float*)d_in[12];
    float* out = (float*)d_out;

    static int attr_set = 0;
    if (!attr_set) {
        cudaFuncSetAttribute(gemm_mma_kernel<0>,
                             cudaFuncAttributeMaxDynamicSharedMemorySize, SMEM_DYN);
        cudaFuncSetAttribute(gemm_mma_kernel<1>,
                             cudaFuncAttributeMaxDynamicSharedMemorySize, SMEM_DYN);
        attr_set = 1;
    }

    __half* w1r; cudaGetSymbolAddress((void**)&w1r, g_w1r);
    __half* w2r; cudaGetSymbolAddress((void**)&w2r, g_w2r);

    zero_counts_kernel<<<1, 32>>>();
    routing_kernel<<<TOKENS, 256>>>(x, rlw, rlb, rw, rb, elw, elb);
    // w1 [e][H][IDIM] -> g_w1r [e][IDIM][H] fp16
    prep_w_kernel<<<dim3(H / 32, IDIM / 32, NE), 256>>>(w1, w1r, H, IDIM);
    // w2 [e][IDIM][H] -> g_w2r [e][H][IDIM] fp16
    prep_w_kernel<<<dim3(IDIM / 32, H / 32, NE), 256>>>(w2, w2r, IDIM, H);
    gemm_mma_kernel<0><<<dim3(IDIM / 256, NE * 32), 256, SMEM_DYN>>>(b1);
    gemm_mma_kernel<1><<<dim3(H / 256, NE * 32, 2), 256, SMEM_DYN>>>(b2);
    finalize_kernel<<<TOKENS, 256>>>(olw, olb, b2, out);
}

// round 11
// speedup vs baseline: 1.8384x; 1.0876x over previous
#include <cuda_runtime.h>
#include <cuda_fp16.h>
#include <math.h>
#include <stdint.h>

#define TOKENS 4096
#define H 1024
#define IDIM 4096
#define NE 8
#define EROWS 4096                      // fixed rows per expert region (worst case)
#define EOSZ ((size_t)NE * EROWS * H)   // one split-K output buffer

// ---------------- scratch (static device globals; no runtime allocation) ----
__device__ __half g_a[(size_t)NE * EROWS * H];       // 67 MB   A for GEMM1 (fp16, K-perm)
__device__ __half g_h[(size_t)NE * EROWS * IDIM];    // 268 MB  gelu out (fp16, K-perm)
__device__ float  g_eo[2 * EOSZ];                    // 268 MB  split-K partial outputs
__device__ __half g_w1r[(size_t)NE * H * IDIM];      // 64 MB   w1 fp16, [e][n][K] K-perm
__device__ __half g_w2r[(size_t)NE * H * IDIM];      // 64 MB   w2 fp16, [e][n][K] K-perm
__device__ int    g_cnt[NE];
__device__ int    g_te[TOKENS * 2];
__device__ int    g_ts[TOKENS * 2];
__device__ float  g_tw[TOKENS * 2];

// ---------------- PTX helpers ----------------------------------------------
__device__ __forceinline__ void cpa16(uint32_t dst, const void* src) {
    asm volatile("cp.async.cg.shared.global [%0], [%1], 16;" :: "r"(dst), "l"(src));
}
__device__ __forceinline__ void cpa_commit() {
    asm volatile("cp.async.commit_group;" ::: "memory");
}
__device__ __forceinline__ void cpa_wait1() {
    asm volatile("cp.async.wait_group 1;" ::: "memory");
}
__device__ __forceinline__ void mma_fp16(float* d, uint32_t a0, uint32_t a1,
                                         uint32_t a2, uint32_t a3,
                                         uint32_t b0, uint32_t b1) {
    asm volatile(
        "mma.sync.aligned.m16n8k16.row.col.f32.f16.f16.f32 "
        "{%0,%1,%2,%3},{%4,%5,%6,%7},{%8,%9},{%0,%1,%2,%3};"
        : "+f"(d[0]), "+f"(d[1]), "+f"(d[2]), "+f"(d[3])
        : "r"(a0), "r"(a1), "r"(a2), "r"(a3), "r"(b0), "r"(b1));
}

// K interleave within each 32-element chunk so per-thread fragments are 16B:
// thread tg owns halfs [tg*8 .. tg*8+7] = {ks0: k=2tg,2tg+1,2tg+8,2tg+9 | ks1: +16}
__device__ __forceinline__ int perm_k(int k) {
    int k16 = k & 15, ks = (k >> 4) & 1;
    int p = (((k16 & 7) >> 1) << 2) | (((k16 >> 3) & 1) << 1) | (k16 & 1);
    int posc = ((p >> 2) << 3) | (ks << 2) | (p & 3);
    return (k & ~31) | posc;
}

// ---------------- routing (+ direct A prep) ---------------------------------
__global__ void zero_counts_kernel() {
    if (threadIdx.x < NE) g_cnt[threadIdx.x] = 0;
}

__global__ void routing_kernel(const float* __restrict__ x,
                               const float* __restrict__ rlw,
                               const float* __restrict__ rlb,
                               const float* __restrict__ rw,
                               const float* __restrict__ rb,
                               const float* __restrict__ elw,
                               const float* __restrict__ elb) {
    int t = blockIdx.x;
    int tid = threadIdx.x;
    __shared__ float xs[H];
    __shared__ float red[8], red2[8];
    __shared__ float logits[NE];
    __shared__ float s_mu, s_rs;
    __shared__ int   se[2], ss[2];

    const float* xrow = x + (size_t)t * H;
    float s = 0.f, s2 = 0.f;
    for (int k = tid; k < H; k += 256) {
        float v = xrow[k];
        xs[k] = v;
        s += v; s2 += v * v;
    }
    for (int o = 16; o; o >>= 1) {
        s  += __shfl_down_sync(~0u, s, o);
        s2 += __shfl_down_sync(~0u, s2, o);
    }
    int w = tid >> 5, l = tid & 31;
    if (l == 0) { red[w] = s; red2[w] = s2; }
    __syncthreads();
    if (tid == 0) {
        float a = 0.f, b = 0.f;
        for (int i = 0; i < 8; i++) { a += red[i]; b += red2[i]; }
        float mu = a * (1.0f / H);
        float var = b * (1.0f / H) - mu * mu;
        s_mu = mu;
        s_rs = rsqrtf(var + 1e-5f);
    }
    __syncthreads();
    float mu = s_mu, rs = s_rs;
    for (int k = tid; k < H; k += 256)
        xs[k] = (xs[k] - mu) * rs;
    __syncthreads();
    if (w < NE) {
        float acc = 0.f;
        for (int k = l; k < H; k += 32) {
            float xln = xs[k] * rlw[k] + rlb[k];
            acc += xln * rw[k * NE + w];
        }
        for (int o = 16; o; o >>= 1) acc += __shfl_down_sync(~0u, acc, o);
        if (l == 0) logits[w] = acc + rb[w];
    }
    __syncthreads();
    if (tid == 0) {
        float v0 = -1e30f, v1 = -1e30f;
        int e0 = 0, e1 = 0;
        for (int e = 0; e < NE; e++) {
            float v = logits[e];
            if (v > v0)      { v1 = v0; e1 = e0; v0 = v; e0 = e; }
            else if (v > v1) { v1 = v;  e1 = e; }
        }
        float tt = expf(v1 - v0);
        float inv = 1.0f / (1.0f + tt);
        int s0 = atomicAdd(&g_cnt[e0], 1);
        int s1 = atomicAdd(&g_cnt[e1], 1);
        se[0] = e0; ss[0] = s0;
        se[1] = e1; ss[1] = s1;
        g_te[2 * t] = e0;     g_ts[2 * t] = s0;     g_tw[2 * t] = inv;
        g_te[2 * t + 1] = e1; g_ts[2 * t + 1] = s1; g_tw[2 * t + 1] = tt * inv;
    }
    __syncthreads();
#pragma unroll
    for (int j = 0; j < 2; j++) {
        int ee = se[j];
        __half* dst = g_a + ((size_t)ee * EROWS + ss[j]) * H;
        const float* lw = elw + (size_t)ee * H;
        const float* lb = elb + (size_t)ee * H;
        for (int k = tid * 2; k < H; k += 512) {
            float f0 = xs[k] * lw[k] + lb[k];
            float f1 = xs[k + 1] * lw[k + 1] + lb[k + 1];
            *(__half2*)(dst + perm_k(k)) = __floats2half2_rn(f0, f1);
        }
    }
}

// Transpose weights [K][N] fp32 -> [N][K] fp16 with K-chunk interleave
__global__ void prep_w_kernel(const float* __restrict__ src,
                              __half* __restrict__ dst, int K, int N) {
    __shared__ float t[32][33];
    int e = blockIdx.z;
    src += (size_t)e * K * N;
    dst += (size_t)e * K * N;
    int k0 = blockIdx.x * 32, n0 = blockIdx.y * 32;
    int idx = threadIdx.x;
    int kr = idx >> 3, nc4 = (idx & 7) * 4;
    float4 v = *(const float4*)(src + (size_t)(k0 + kr) * N + n0 + nc4);
    t[kr][nc4 + 0] = v.x; t[kr][nc4 + 1] = v.y;
    t[kr][nc4 + 2] = v.z; t[kr][nc4 + 3] = v.w;
    __syncthreads();
    int n = idx >> 3;
    int p0 = (idx & 7) * 2;
#pragma unroll
    for (int j = 0; j < 2; j++) {
        int kp = (p0 + j) * 2;
        __half2 h = __floats2half2_rn(t[kp][n], t[kp + 1][n]);
        *(__half2*)(dst + (size_t)(n0 + n) * K + perm_k(k0 + kp)) = h;
    }
}

// ---------------- grouped GEMM via mma.sync fp16 ----------------------------
// Block tile 128x256, BK=64, 3-stage cp.async ring, one barrier per chunk,
// 8 warps = 2(M) x 4(N), warp tile 64x64. Row-parity XOR swizzle for smem.
#define ATILE_B 16384               // 128 rows * 128 B
#define BTILE_B 32768               // 256 rows * 128 B
#define STGB (ATILE_B + BTILE_B)    // 49152
#define SMEM_DYN (3 * STGB)         // 147456 bytes

// MODE 0: GEMM1 A=g_a (K=1024), B=g_w1r, out=g_h (bias+gelu, fp16 K-perm)
// MODE 1: GEMM2 A=g_h (K=4096 split z*2048), B=g_w2r, out=g_eo[z] fp32
template <int MODE>
__global__ void __launch_bounds__(256, 1)
gemm_mma_kernel(const float* __restrict__ bias) {
    extern __shared__ char smc[];
    const int KTOT = (MODE == 0) ? H : IDIM;
    const int Kz   = (MODE == 0) ? H : (IDIM / 2);
    const int NO   = (MODE == 0) ? IDIM : H;

    int e = blockIdx.y >> 5;
    int mrow = (blockIdx.y & 31) << 7;
    int cnt = g_cnt[e];
    if (mrow >= cnt) return;
    int z = (MODE == 0) ? 0 : blockIdx.z;
    int k0 = z * Kz;
    int colBase = blockIdx.x * 256;

    const __half* Asrc = ((MODE == 0) ? g_a : g_h)
                       + (size_t)(e * EROWS + mrow) * KTOT + k0;
    const __half* Bsrc = ((MODE == 0) ? g_w1r : g_w2r)
                       + (size_t)e * ((size_t)H * IDIM)
                       + (size_t)colBase * KTOT + k0;

    int tid = threadIdx.x, lane = tid & 31, warp = tid >> 5;
    int wm = (warp & 1) << 6, wn = (warp >> 1) << 6;
    int g = lane >> 2, tg = lane & 3;

    uint32_t sU = (uint32_t)__cvta_generic_to_shared(smc);

    float acc[4][8][4];
#pragma unroll
    for (int mi = 0; mi < 4; mi++)
#pragma unroll
        for (int ni = 0; ni < 8; ni++)
#pragma unroll
            for (int q = 0; q < 4; q++) acc[mi][ni][q] = 0.f;

    const int NC = Kz / 64;

    auto issue = [&](int c) {
        uint32_t st = sU + (uint32_t)((c % 3) * STGB);
        const __half* ag = Asrc + c * 64;
#pragma unroll
        for (int j = 0; j < 4; j++) {
            int q = tid + 256 * j;
            int r = q >> 3, o = q & 7;
            uint32_t ph = (uint32_t)(r * 128 + ((o * 16) ^ ((r & 1) << 6)));
            cpa16(st + ph, ag + (size_t)r * KTOT + o * 8);
        }
        uint32_t bt = st + ATILE_B;
        const __half* bg = Bsrc + c * 64;
#pragma unroll
        for (int j = 0; j < 8; j++) {
            int q = tid + 256 * j;
            int r = q >> 3, o = q & 7;
            uint32_t ph = (uint32_t)(r * 128 + ((o * 16) ^ ((r & 1) << 6)));
            cpa16(bt + ph, bg + (size_t)r * KTOT + o * 8);
        }
    };

    issue(0); cpa_commit();
    issue(1); cpa_commit();

    for (int c = 0; c < NC; c++) {
        cpa_wait1();
        __syncthreads();
        if (c + 2 < NC) issue(c + 2);
        cpa_commit();

        const char* As = smc + (c % 3) * STGB;
        const char* Bb = As + ATILE_B;
#pragma unroll
        for (int kc = 0; kc < 2; kc++) {
            int inner = kc * 64 + tg * 16;
            uint4 Au[4][2];
#pragma unroll
            for (int mi = 0; mi < 4; mi++) {
                int r0 = wm + 16 * mi + g;
                int r1 = r0 + 8;
                Au[mi][0] = *(const uint4*)(As + r0 * 128 + (inner ^ ((r0 & 1) << 6)));
                Au[mi][1] = *(const uint4*)(As + r1 * 128 + (inner ^ ((r1 & 1) << 6)));
            }
#pragma unroll
            for (int ni = 0; ni < 8; ni++) {
                int rb = wn + 8 * ni + g;
                uint4 Bv = *(const uint4*)(Bb + rb * 128 + (inner ^ ((rb & 1) << 6)));
#pragma unroll
                for (int mi = 0; mi < 4; mi++) {
                    mma_fp16(acc[mi][ni], Au[mi][0].x, Au[mi][1].x,
                             Au[mi][0].y, Au[mi][1].y, Bv.x, Bv.y);
                    mma_fp16(acc[mi][ni], Au[mi][0].z, Au[mi][1].z,
                             Au[mi][0].w, Au[mi][1].w, Bv.z, Bv.w);
                }
            }
        }
    }

    // ---------------- epilogue ----------------
#pragma unroll
    for (int mi = 0; mi < 4; mi++) {
        int lr0 = mrow + wm + 16 * mi + g;
        int lr1 = lr0 + 8;
        bool live0 = lr0 < cnt;
        bool live1 = lr1 < cnt;
        size_t grow0 = (size_t)(e * EROWS) + lr0;
        size_t grow1 = (size_t)(e * EROWS) + lr1;
#pragma unroll
        for (int ni = 0; ni < 8; ni++) {
            int gc = colBase + wn + 8 * ni + 2 * tg;
            float v0 = acc[mi][ni][0];
            float v1 = acc[mi][ni][1];
            float v2 = acc[mi][ni][2];
            float v3 = acc[mi][ni][3];
            if (MODE == 0) {
                float bv0 = bias[(size_t)e * NO + gc];
                float bv1 = bias[(size_t)e * NO + gc + 1];
                v0 += bv0; v1 += bv1; v2 += bv0; v3 += bv1;
                v0 = 0.5f * v0 * (1.0f + erff(v0 * 0.70710678118654752f));
                v1 = 0.5f * v1 * (1.0f + erff(v1 * 0.70710678118654752f));
                v2 = 0.5f * v2 * (1.0f + erff(v2 * 0.70710678118654752f));
                v3 = 0.5f * v3 * (1.0f + erff(v3 * 0.70710678118654752f));
                int i0 = perm_k(gc);
                if (live0)
                    *(__half2*)(g_h + grow0 * IDIM + i0) = __floats2half2_rn(v0, v1);
                if (live1)
                    *(__half2*)(g_h + grow1 * IDIM + i0) = __floats2half2_rn(v2, v3);
            } else {
                float* outp = g_eo + (size_t)z * EOSZ;
                if (live0) *(float2*)(outp + grow0 * H + gc) = make_float2(v0, v1);
                if (live1) *(float2*)(outp + grow1 * H + gc) = make_float2(v2, v3);
            }
        }
    }
}

// ---------------- finalize ---------------------------------------------------
__global__ void finalize_kernel(const float* __restrict__ olw,
                                const float* __restrict__ olb,
                                const float* __restrict__ b2,
                                float* __restrict__ out) {
    int t = blockIdx.x;
    int tid = threadIdx.x;
    __shared__ float cs[H];
    __shared__ float red[8], red2[8];
    __shared__ float s_mu, s_rs;

    int e0 = g_te[2 * t], e1 = g_te[2 * t + 1];
    size_t row0 = (size_t)e0 * EROWS + g_ts[2 * t];
    size_t row1 = (size_t)e1 * EROWS + g_ts[2 * t + 1];
    float w0 = g_tw[2 * t], w1v = g_tw[2 * t + 1];
    const float* rA0 = g_eo + row0 * H;
    const float* rB0 = g_eo + EOSZ + row0 * H;
    const float* rA1 = g_eo + row1 * H;
    const float* rB1 = g_eo + EOSZ + row1 * H;
    const float* bb0 = b2 + (size_t)e0 * H;
    const float* bb1 = b2 + (size_t)e1 * H;

    float s = 0.f, s2 = 0.f;
    for (int k = tid; k < H; k += 256) {
        float u0 = rA0[k] + rB0[k] + bb0[k];
        float u1 = rA1[k] + rB1[k] + bb1[k];
        float v = w0 * u0 + w1v * u1;
        cs[k] = v;
        s += v; s2 += v * v;
    }
    for (int o = 16; o; o >>= 1) {
        s  += __shfl_down_sync(~0u, s, o);
        s2 += __shfl_down_sync(~0u, s2, o);
    }
    int w = tid >> 5, l = tid & 31;
    if (l == 0) { red[w] = s; red2[w] = s2; }
    __syncthreads();
    if (tid == 0) {
        float a = 0.f, b = 0.f;
        for (int i = 0; i < 8; i++) { a += red[i]; b += red2[i]; }
        float mu = a * (1.0f / H);
        float var = b * (1.0f / H) - mu * mu;
        s_mu = mu;
        s_rs = rsqrtf(var + 1e-5f);
    }
    __syncthreads();
    float mu = s_mu, rs = s_rs;
    for (int k = tid; k < H; k += 256) {
        out[(size_t)t * H + k] = (cs[k] - mu) * rs * olw[k] + olb[k];
    }
}

// ---------------- launch -----------------------------------------------------
extern "C" void kernel_launch(void* const* d_in, const int* in_sizes, int n_in,
                              void* d_out, int out_size) {
    const float* x   = (const float*)d_in[0];
    const float* rlw = (const float*)d_in[1];
    const float* rlb = (const float*)d_in[2];
    const float* rw  = (const float*)d_in[3];
    const float* rb  = (const float*)d_in[4];
    const float* elw = (const float*)d_in[5];
    const float* elb = (const float*)d_in[6];
    const float* w1  = (const float*)d_in[7];
    const float* b1  = (const float*)d_in[8];
    const float* w2  = (const float*)d_in[9];
    const float* b2  = (const float*)d_in[10];
    const float* olw = (const float*)d_in[11];
    const float* olb = (const float*)d_in[12];
    float* out = (float*)d_out;

    static int attr_set = 0;
    if (!attr_set) {
        cudaFuncSetAttribute(gemm_mma_kernel<0>,
                             cudaFuncAttributeMaxDynamicSharedMemorySize, SMEM_DYN);
        cudaFuncSetAttribute(gemm_mma_kernel<1>,
                             cudaFuncAttributeMaxDynamicSharedMemorySize, SMEM_DYN);
        attr_set = 1;
    }

    __half* w1r; cudaGetSymbolAddress((void**)&w1r, g_w1r);
    __half* w2r; cudaGetSymbolAddress((void**)&w2r, g_w2r);

    zero_counts_kernel<<<1, 32>>>();
    routing_kernel<<<TOKENS, 256>>>(x, rlw, rlb, rw, rb, elw, elb);
    // w1 [e][H][IDIM] -> g_w1r [e][IDIM][H] fp16
    prep_w_kernel<<<dim3(H / 32, IDIM / 32, NE), 256>>>(w1, w1r, H, IDIM);
    // w2 [e][IDIM][H] -> g_w2r [e][H][IDIM] fp16
    prep_w_kernel<<<dim3(IDIM / 32, H / 32, NE), 256>>>(w2, w2r, IDIM, H);
    gemm_mma_kernel<0><<<dim3(IDIM / 256, NE * 32), 256, SMEM_DYN>>>(b1);
    gemm_mma_kernel<1><<<dim3(H / 256, NE * 32, 2), 256, SMEM_DYN>>>(b2);
    finalize_kernel<<<TOKENS, 256>>>(olw, olb, b2, out);
}